// round 4
// baseline (speedup 1.0000x reference)
#include <cuda_runtime.h>
#include <math.h>

#define HDIM 256
#define WDIM 256
#define WF   129
#define BSZ  4
#define CSZ  128
#define NBLK 8

// scratch spectrum buffer, layout [b, c, wf, h] as float2 (~135 MB)
__device__ float2 g_buf[(size_t)BSZ * CSZ * WF * HDIM];

__device__ __forceinline__ float2 cadd(float2 a, float2 b){ return make_float2(a.x+b.x, a.y+b.y); }
__device__ __forceinline__ float2 csub(float2 a, float2 b){ return make_float2(a.x-b.x, a.y-b.y); }
__device__ __forceinline__ float2 cmul(float2 a, float2 b){
    return make_float2(a.x*b.x - a.y*b.y, a.x*b.y + a.y*b.x);
}
__device__ __forceinline__ float2 cmulc(float2 a, float2 b){  // a * conj(b)
    return make_float2(a.x*b.x + a.y*b.y, a.y*b.x - a.x*b.y);
}

// packed f32x2 helpers (FFMA2: 2 fp32 FMAs per issue slot)
__device__ __forceinline__ double pk(float lo, float hi){
    double d; asm("mov.b64 %0, {%1, %2};" : "=d"(d) : "f"(lo), "f"(hi)); return d;
}
__device__ __forceinline__ void upk(double d, float& lo, float& hi){
    asm("mov.b64 {%0, %1}, %2;" : "=f"(lo), "=f"(hi) : "d"(d));
}
__device__ __forceinline__ double ffma2(double a, double b, double c){
    double r; asm("fma.rn.f32x2 %0, %1, %2, %3;" : "=d"(r) : "d"(a), "d"(b), "d"(c));
    return r;
}

// multiply by (-i) forward, (+i) inverse
template<bool INV>
__device__ __forceinline__ float2 mul_i(float2 a){
    return INV ? make_float2(-a.y, a.x) : make_float2(a.y, -a.x);
}

template<bool INV>
__device__ __forceinline__ void bf4(float2& x0, float2& x1, float2& x2, float2& x3){
    float2 t0 = cadd(x0, x2), t1 = csub(x0, x2);
    float2 t2 = cadd(x1, x3), t3 = csub(x1, x3);
    float2 j3 = mul_i<INV>(t3);
    x0 = cadd(t0, t2);
    x2 = csub(t0, t2);
    x1 = cadd(t1, j3);
    x3 = csub(t1, j3);
}

// In-register 16-point DFT (radix-4 x radix-4). Input v[n] natural order.
// Output: bin k = c + 4d lands in slot 4c + d  (slot(k) = ((k&3)<<2)|(k>>2)).
template<bool INV>
__device__ __forceinline__ void dft16(float2 v[16]){
    const float S = INV ? 1.f : -1.f;
    const float2 W1 = make_float2( 0.92387953251128674f, S*0.38268343236508978f);
    const float2 W2 = make_float2( 0.70710678118654752f, S*0.70710678118654752f);
    const float2 W3 = make_float2( 0.38268343236508978f, S*0.92387953251128674f);
    const float2 W6 = make_float2(-0.70710678118654752f, S*0.70710678118654752f);
    const float2 W9 = make_float2(-0.92387953251128674f, -S*0.38268343236508978f);

    bf4<INV>(v[0], v[4], v[8],  v[12]);
    bf4<INV>(v[1], v[5], v[9],  v[13]);
    bf4<INV>(v[2], v[6], v[10], v[14]);
    bf4<INV>(v[3], v[7], v[11], v[15]);
    v[5]  = cmul(v[5],  W1);
    v[9]  = cmul(v[9],  W2);
    v[13] = cmul(v[13], W3);
    v[6]  = cmul(v[6],  W2);
    v[10] = mul_i<INV>(v[10]);           // W16^4 = -/+ i
    v[14] = cmul(v[14], W6);
    v[7]  = cmul(v[7],  W3);
    v[11] = cmul(v[11], W6);
    v[15] = cmul(v[15], W9);
    bf4<INV>(v[0],  v[1],  v[2],  v[3]);
    bf4<INV>(v[4],  v[5],  v[6],  v[7]);
    bf4<INV>(v[8],  v[9],  v[10], v[11]);
    bf4<INV>(v[12], v[13], v[14], v[15]);
}

#define SLOT(k) ((((k) & 3) << 2) | ((k) >> 2))

__device__ __forceinline__ void build_tw(float2* tw, int tid){
    float s, c;
    sincosf((float)tid * (-6.283185307179586f / 256.f), &s, &c);
    tw[tid] = make_float2(c, s);
}

// ---------------------------------------------------------------------------
// K1: row rfft. CTA = 32 rows of one (b,c) image, packed 2 real rows / complex
// FFT (16 FFTs, 16 threads each). Output transposed [b,c,wf,h], scaled 1/256.
// ---------------------------------------------------------------------------
__global__ void __launch_bounds__(256) k_rowfft(const float* __restrict__ x){
    extern __shared__ char smraw[];
    float2* sbuf = (float2*)smraw;                 // 4352 float2 (T:272/fft, S:257/fft)
    float2* tw   = (float2*)(smraw + 34816);       // 256 float2

    const int tid = threadIdx.x;
    const int f = tid >> 4, t = tid & 15;
    const int bc = blockIdx.x >> 3;
    const int h0 = (blockIdx.x & 7) << 5;

    build_tw(tw, tid);

    const float* r0 = x + ((size_t)bc * HDIM + h0 + 2 * f) * WDIM;
    float2 v[16];
#pragma unroll
    for (int n1 = 0; n1 < 16; n1++)
        v[n1] = make_float2(r0[16 * n1 + t], r0[WDIM + 16 * n1 + t]);
    dft16<false>(v);
    __syncthreads();                               // tw ready

#pragma unroll
    for (int k1 = 0; k1 < 16; k1++){
        float2 bv = v[SLOT(k1)];
        if (k1) bv = cmul(bv, tw[t * k1]);
        sbuf[f * 272 + k1 * 17 + t] = bv;
    }
    __syncthreads();
#pragma unroll
    for (int n2 = 0; n2 < 16; n2++)
        v[n2] = sbuf[f * 272 + t * 17 + n2];
    __syncthreads();                               // T reads done before S writes
    dft16<false>(v);
#pragma unroll
    for (int k2 = 0; k2 < 16; k2++)
        sbuf[f * 257 + t + 16 * k2] = v[SLOT(k2)];
    __syncthreads();

    float2* dst = g_buf + (size_t)bc * WF * HDIM;
    for (int e = tid; e < WF * 32; e += 256){
        const int wf = e >> 5, r = e & 31, fp = r >> 1;
        float2 Z1 = sbuf[fp * 257 + wf];
        float2 Z2 = sbuf[fp * 257 + ((256 - wf) & 255)];
        float2 val = (r & 1)
            ? make_float2((Z1.y + Z2.y) * 0.5f, (Z2.x - Z1.x) * 0.5f)
            : make_float2((Z1.x + Z2.x) * 0.5f, (Z1.y - Z2.y) * 0.5f);
        dst[(size_t)wf * HDIM + h0 + r] =
            make_float2(val.x * (1.f / 256.f), val.y * (1.f / 256.f));
    }
}

// ---------------------------------------------------------------------------
// K2: column FFT over h (16 channels of one block), per-bin block MLP with
// packed f32x2 FMAs, inverse column FFT. In-place on g_buf.
// T (transpose scratch, stride 272) and A (spectrum, stride 257) ALIAS the
// same smem buffer; extra __syncthreads separate their live ranges.
// ---------------------------------------------------------------------------
__global__ void __launch_bounds__(256) k_colfft_mlp(
        const float* __restrict__ w1g, const float* __restrict__ b1g,
        const float* __restrict__ w2g, const float* __restrict__ b2g){
    extern __shared__ char smraw[];
    float2*  buf = (float2*)smraw;                 // 4352 f2   [0, 34816)
    float2*  tw  = (float2*)(smraw + 34816);       // 256 f2    [34816, 36864)
    double2* w1p = (double2*)(smraw + 36864);      // 256 d2    [36864, 40960)
    double2* w2p = (double2*)(smraw + 40960);      // 256 d2    [40960, 45056)
    double*  b1p = (double*)(smraw + 45056);       // 16 d      [45056, 45184)
    double*  b2p = (double*)(smraw + 45184);       // 16 d      [45184, 45312)

    const int tid = threadIdx.x;
    const int f = tid >> 4, t = tid & 15;
    const int wf = blockIdx.x % WF;
    const int bk = blockIdx.x / WF;
    const int k = bk & 7, b = bk >> 3;

    build_tw(tw, tid);
    {   // weights: w1/w2 are [2][8][16][16] (i-major, o-minor), duplicate-packed
        float wr = w1g[k * 256 + tid], wi = w1g[2048 + k * 256 + tid];
        w1p[tid] = make_double2(pk(wr, wr), pk(wi, wi));
        wr = w2g[k * 256 + tid]; wi = w2g[2048 + k * 256 + tid];
        w2p[tid] = make_double2(pk(wr, wr), pk(wi, wi));
    }
    if (tid < 16){
        b1p[tid] = pk(b1g[k * 16 + tid], b1g[128 + k * 16 + tid]);
        b2p[tid] = pk(b2g[k * 16 + tid], b2g[128 + k * 16 + tid]);
    }

    float2* chp = g_buf + ((size_t)(b * CSZ + k * 16 + f) * WF + wf) * HDIM;

    float2 v[16];
#pragma unroll
    for (int n1 = 0; n1 < 16; n1++) v[n1] = chp[16 * n1 + t];
    dft16<false>(v);
    __syncthreads();                               // tw + weights ready
#pragma unroll
    for (int k1 = 0; k1 < 16; k1++){
        float2 bv = v[SLOT(k1)];
        if (k1) bv = cmul(bv, tw[t * k1]);
        buf[f * 272 + k1 * 17 + t] = bv;           // T write
    }
    __syncthreads();
#pragma unroll
    for (int n2 = 0; n2 < 16; n2++) v[n2] = buf[f * 272 + t * 17 + n2];  // T read
    __syncthreads();                               // T dead -> reuse as A
    dft16<false>(v);
#pragma unroll
    for (int k2 = 0; k2 < 16; k2++)
        buf[f * 257 + t + 16 * k2] = v[SLOT(k2)];  // A write
    __syncthreads();

    // ---- MLP: one thread per h-bin, packed f32x2 complex GEMV ----
    {
        double xp[16];
#pragma unroll
        for (int i = 0; i < 16; i++){
            float2 q = buf[i * 257 + tid];         // A read (column tid only)
            xp[i] = pk(q.x, q.y);
        }
        double o1p[16];
#pragma unroll
        for (int o = 0; o < 16; o++){
            double Aa = b1p[o], Bb = 0.;   // 0.0 == packed (0.f, 0.f)
#pragma unroll
            for (int i = 0; i < 16; i++){
                double2 w = w1p[i * 16 + o];
                Aa = ffma2(xp[i], w.x, Aa);
                Bb = ffma2(xp[i], w.y, Bb);
            }
            float alo, ahi, blo, bhi;
            upk(Aa, alo, ahi); upk(Bb, blo, bhi);
            o1p[o] = pk(fmaxf(alo - bhi, 0.f), fmaxf(ahi + blo, 0.f));
        }
#pragma unroll
        for (int o = 0; o < 16; o++){
            double Aa = b2p[o], Bb = 0.;
#pragma unroll
            for (int i = 0; i < 16; i++){
                double2 w = w2p[i * 16 + o];
                Aa = ffma2(o1p[i], w.x, Aa);
                Bb = ffma2(o1p[i], w.y, Bb);
            }
            float alo, ahi, blo, bhi;
            upk(Aa, alo, ahi); upk(Bb, blo, bhi);
            const float ar = alo - bhi, ai = ahi + blo;
            const float sr = copysignf(fmaxf(fabsf(ar) - 0.01f, 0.f), ar);
            const float si = copysignf(fmaxf(fabsf(ai) - 0.01f, 0.f), ai);
            float xr, xi; upk(xp[o], xr, xi);
            buf[o * 257 + tid] = make_float2(sr * xr - si * xi,
                                             sr * xi + si * xr);  // A write
        }
    }
    __syncthreads();

    // ---- inverse column FFT (bin-strided in, coalesced time-domain out) ----
#pragma unroll
    for (int k2 = 0; k2 < 16; k2++) v[k2] = buf[f * 257 + t + 16 * k2];  // A read
    __syncthreads();                               // A dead -> reuse as T
    dft16<true>(v);
#pragma unroll
    for (int m2 = 0; m2 < 16; m2++){
        float2 q = v[SLOT(m2)];
        if (m2) q = cmulc(q, tw[m2 * t]);
        buf[f * 272 + m2 * 17 + t] = q;            // T write
    }
    __syncthreads();
#pragma unroll
    for (int n = 0; n < 16; n++) v[n] = buf[f * 272 + t * 17 + n];       // T read
    dft16<true>(v);
#pragma unroll
    for (int m1 = 0; m1 < 16; m1++)
        chp[16 * m1 + t] = v[SLOT(m1)];
}

// ---------------------------------------------------------------------------
// K3: row irfft. CTA = 32 rows of one (b,c) image, 2 rows packed per inverse
// complex FFT. Hermitian extension + edge-bin imag zeroing == irfft semantics.
// Scale 1/256, add residual.
// ---------------------------------------------------------------------------
__global__ void __launch_bounds__(256) k_rowifft(const float* __restrict__ x,
                                                 float* __restrict__ out){
    extern __shared__ char smraw[];
    float2* sbuf = (float2*)smraw;                 // 4352 f2
    float2* tw   = (float2*)(smraw + 34816);       // 256 f2

    const int tid = threadIdx.x;
    const int f = tid >> 4, t = tid & 15;
    const int bc = blockIdx.x >> 3;
    const int h0 = (blockIdx.x & 7) << 5;

    build_tw(tw, tid);

    const float2* gsrc = g_buf + (size_t)bc * WF * HDIM;
    // Build packed full spectrum Z[f][0..255], Z = X0 + i*X1
    for (int e = tid; e < WF * 16; e += 256){
        const int wf = e >> 4, fp = e & 15;
        float4 q = *(const float4*)(gsrc + (size_t)wf * HDIM + h0 + 2 * fp);
        float ay = q.y, by = q.w;
        if (wf == 0 || wf == 128){ ay = 0.f; by = 0.f; }   // irfft ignores edge imag
        sbuf[fp * 257 + wf] = make_float2(q.x - by, ay + q.z);
        if (wf >= 1 && wf <= 127)
            sbuf[fp * 257 + 256 - wf] = make_float2(q.x + by, q.z - ay);
    }
    __syncthreads();

    float2 v[16];
#pragma unroll
    for (int k2 = 0; k2 < 16; k2++) v[k2] = sbuf[f * 257 + t + 16 * k2];
    __syncthreads();                               // S reads done before T writes
    dft16<true>(v);
#pragma unroll
    for (int m2 = 0; m2 < 16; m2++){
        float2 q = v[SLOT(m2)];
        if (m2) q = cmulc(q, tw[m2 * t]);
        sbuf[f * 272 + m2 * 17 + t] = q;
    }
    __syncthreads();
#pragma unroll
    for (int n = 0; n < 16; n++) v[n] = sbuf[f * 272 + t * 17 + n];
    dft16<true>(v);

    const float* bias0 = x   + ((size_t)bc * HDIM + h0 + 2 * f) * WDIM;
    float*       o0    = out + ((size_t)bc * HDIM + h0 + 2 * f) * WDIM;
#pragma unroll
    for (int m1 = 0; m1 < 16; m1++){
        float2 z = v[SLOT(m1)];
        const int w_ = 16 * m1 + t;
        o0[w_]        = z.x * (1.f / 256.f) + bias0[w_];
        o0[WDIM + w_] = z.y * (1.f / 256.f) + bias0[WDIM + w_];
    }
}

extern "C" void kernel_launch(void* const* d_in, const int* in_sizes, int n_in,
                              void* d_out, int out_size) {
    const float* x  = (const float*)d_in[0];
    const float* w1 = (const float*)d_in[1];
    const float* b1 = (const float*)d_in[2];
    const float* w2 = (const float*)d_in[3];
    const float* b2 = (const float*)d_in[4];
    float* out = (float*)d_out;

    const int SMEM_ROW = 34816 + 2048;             // 36864
    const int SMEM_COL = 45312;

    cudaFuncSetAttribute(k_rowfft,     cudaFuncAttributeMaxDynamicSharedMemorySize, SMEM_ROW);
    cudaFuncSetAttribute(k_colfft_mlp, cudaFuncAttributeMaxDynamicSharedMemorySize, SMEM_COL);
    cudaFuncSetAttribute(k_rowifft,    cudaFuncAttributeMaxDynamicSharedMemorySize, SMEM_ROW);

    k_rowfft<<<BSZ * CSZ * (HDIM / 32), 256, SMEM_ROW>>>(x);
    k_colfft_mlp<<<BSZ * NBLK * WF, 256, SMEM_COL>>>(w1, b1, w2, b2);
    k_rowifft<<<BSZ * CSZ * (HDIM / 32), 256, SMEM_ROW>>>(x, out);
}

// round 6
// speedup vs baseline: 1.4173x; 1.4173x over previous
#include <cuda_runtime.h>
#include <cuda_fp16.h>
#include <math.h>

#define HDIM 256
#define WDIM 256
#define WF   129
#define BSZ  4
#define CSZ  128
#define NBLK 8

// scratch spectrum buffer, layout [b, c, wf, h] as half2 (~67 MB)
__device__ __half2 g_buf[(size_t)BSZ * CSZ * WF * HDIM];

__device__ __forceinline__ float2 cadd(float2 a, float2 b){ return make_float2(a.x+b.x, a.y+b.y); }
__device__ __forceinline__ float2 csub(float2 a, float2 b){ return make_float2(a.x-b.x, a.y-b.y); }
__device__ __forceinline__ float2 cmul(float2 a, float2 b){
    return make_float2(a.x*b.x - a.y*b.y, a.x*b.y + a.y*b.x);
}
__device__ __forceinline__ float2 cmulc(float2 a, float2 b){  // a * conj(b)
    return make_float2(a.x*b.x + a.y*b.y, a.y*b.x - a.x*b.y);
}

// multiply by (-i) forward, (+i) inverse
template<bool INV>
__device__ __forceinline__ float2 mul_i(float2 a){
    return INV ? make_float2(-a.y, a.x) : make_float2(a.y, -a.x);
}

template<bool INV>
__device__ __forceinline__ void bf4(float2& x0, float2& x1, float2& x2, float2& x3){
    float2 t0 = cadd(x0, x2), t1 = csub(x0, x2);
    float2 t2 = cadd(x1, x3), t3 = csub(x1, x3);
    float2 j3 = mul_i<INV>(t3);
    x0 = cadd(t0, t2);
    x2 = csub(t0, t2);
    x1 = cadd(t1, j3);
    x3 = csub(t1, j3);
}

// In-register 16-point DFT (radix-4 x radix-4). Input v[n] natural order.
// Output: bin k = c + 4d lands in slot 4c + d  (slot(k) = ((k&3)<<2)|(k>>2)).
template<bool INV>
__device__ __forceinline__ void dft16(float2 v[16]){
    const float S = INV ? 1.f : -1.f;
    const float2 W1 = make_float2( 0.92387953251128674f, S*0.38268343236508978f);
    const float2 W2 = make_float2( 0.70710678118654752f, S*0.70710678118654752f);
    const float2 W3 = make_float2( 0.38268343236508978f, S*0.92387953251128674f);
    const float2 W6 = make_float2(-0.70710678118654752f, S*0.70710678118654752f);
    const float2 W9 = make_float2(-0.92387953251128674f, -S*0.38268343236508978f);

    bf4<INV>(v[0], v[4], v[8],  v[12]);
    bf4<INV>(v[1], v[5], v[9],  v[13]);
    bf4<INV>(v[2], v[6], v[10], v[14]);
    bf4<INV>(v[3], v[7], v[11], v[15]);
    v[5]  = cmul(v[5],  W1);
    v[9]  = cmul(v[9],  W2);
    v[13] = cmul(v[13], W3);
    v[6]  = cmul(v[6],  W2);
    v[10] = mul_i<INV>(v[10]);           // W16^4 = -/+ i
    v[14] = cmul(v[14], W6);
    v[7]  = cmul(v[7],  W3);
    v[11] = cmul(v[11], W6);
    v[15] = cmul(v[15], W9);
    bf4<INV>(v[0],  v[1],  v[2],  v[3]);
    bf4<INV>(v[4],  v[5],  v[6],  v[7]);
    bf4<INV>(v[8],  v[9],  v[10], v[11]);
    bf4<INV>(v[12], v[13], v[14], v[15]);
}

#define SLOT(k) ((((k) & 3) << 2) | ((k) >> 2))

__device__ __forceinline__ void build_tw(float2* tw, int tid){
    float s, c;
    sincosf((float)tid * (-6.283185307179586f / 256.f), &s, &c);
    tw[tid] = make_float2(c, s);
}

// ---------------------------------------------------------------------------
// K1: row rfft. CTA = 32 rows of one (b,c) image, packed 2 real rows / complex
// FFT (16 FFTs, 16 threads each). Output transposed [b,c,wf,h] half2, x 1/256.
// ---------------------------------------------------------------------------
__global__ void __launch_bounds__(256) k_rowfft(const float* __restrict__ x){
    extern __shared__ char smraw[];
    float2* sbuf = (float2*)smraw;                 // 4352 float2 (T:272/fft, S:257/fft)
    float2* tw   = (float2*)(smraw + 34816);       // 256 float2

    const int tid = threadIdx.x;
    const int f = tid >> 4, t = tid & 15;
    const int bc = blockIdx.x >> 3;
    const int h0 = (blockIdx.x & 7) << 5;

    build_tw(tw, tid);

    const float* r0 = x + ((size_t)bc * HDIM + h0 + 2 * f) * WDIM;
    float2 v[16];
#pragma unroll
    for (int n1 = 0; n1 < 16; n1++)
        v[n1] = make_float2(r0[16 * n1 + t], r0[WDIM + 16 * n1 + t]);
    dft16<false>(v);
    __syncthreads();                               // tw ready

#pragma unroll
    for (int k1 = 0; k1 < 16; k1++){
        float2 bv = v[SLOT(k1)];
        if (k1) bv = cmul(bv, tw[t * k1]);
        sbuf[f * 272 + k1 * 17 + t] = bv;
    }
    __syncthreads();
#pragma unroll
    for (int n2 = 0; n2 < 16; n2++)
        v[n2] = sbuf[f * 272 + t * 17 + n2];
    __syncthreads();                               // T reads done before S writes
    dft16<false>(v);
#pragma unroll
    for (int k2 = 0; k2 < 16; k2++)
        sbuf[f * 257 + t + 16 * k2] = v[SLOT(k2)];
    __syncthreads();

    __half2* dst = g_buf + (size_t)bc * WF * HDIM;
    for (int e = tid; e < WF * 32; e += 256){
        const int wf = e >> 5, r = e & 31, fp = r >> 1;
        float2 Z1 = sbuf[fp * 257 + wf];
        float2 Z2 = sbuf[fp * 257 + ((256 - wf) & 255)];
        float2 val = (r & 1)
            ? make_float2((Z1.y + Z2.y) * 0.5f, (Z2.x - Z1.x) * 0.5f)
            : make_float2((Z1.x + Z2.x) * 0.5f, (Z1.y - Z2.y) * 0.5f);
        dst[(size_t)wf * HDIM + h0 + r] =
            __floats2half2_rn(val.x * (1.f / 256.f), val.y * (1.f / 256.f));
    }
}

// ---------------------------------------------------------------------------
// K2: column FFT over h (16 channels of one block), per-bin block MLP with
// packed half2 HFMA2, inverse column FFT. In-place on g_buf (half2).
// T (stride 272) and A (stride 257) alias one smem buffer.
// ---------------------------------------------------------------------------
__global__ void __launch_bounds__(256) k_colfft_mlp(
        const float* __restrict__ w1g, const float* __restrict__ b1g,
        const float* __restrict__ w2g, const float* __restrict__ b2g){
    extern __shared__ char smraw[];
    float2*  buf = (float2*)smraw;                 // 4352 f2   [0, 34816)
    float2*  tw  = (float2*)(smraw + 34816);       // 256 f2    [34816, 36864)
    uint2*   w1h = (uint2*)(smraw + 36864);        // 256 u2    [36864, 38912)
    uint2*   w2h = (uint2*)(smraw + 38912);        // 256 u2    [38912, 40960)
    float2*  b1c = (float2*)(smraw + 40960);       // 16 f2
    float2*  b2c = (float2*)(smraw + 41088);       // 16 f2     end 41216

    const int tid = threadIdx.x;
    const int f = tid >> 4, t = tid & 15;
    const int wf = blockIdx.x % WF;
    const int bk = blockIdx.x / WF;
    const int k = bk & 7, b = bk >> 3;

    build_tw(tw, tid);
    {   // weights: w1/w2 are [2][8][16][16] (i-major, o-minor), duplicate-packed
        float wr = w1g[k * 256 + tid], wi = w1g[2048 + k * 256 + tid];
        __half2 hr = __floats2half2_rn(wr, wr), hi = __floats2half2_rn(wi, wi);
        uint2 u;
        u.x = *(unsigned int*)&hr;
        u.y = *(unsigned int*)&hi;
        w1h[tid] = u;
        wr = w2g[k * 256 + tid]; wi = w2g[2048 + k * 256 + tid];
        hr = __floats2half2_rn(wr, wr); hi = __floats2half2_rn(wi, wi);
        u.x = *(unsigned int*)&hr;
        u.y = *(unsigned int*)&hi;
        w2h[tid] = u;
    }
    if (tid < 16){
        b1c[tid] = make_float2(b1g[k * 16 + tid], b1g[128 + k * 16 + tid]);
        b2c[tid] = make_float2(b2g[k * 16 + tid], b2g[128 + k * 16 + tid]);
    }

    __half2* chp = g_buf + ((size_t)(b * CSZ + k * 16 + f) * WF + wf) * HDIM;

    float2 v[16];
#pragma unroll
    for (int n1 = 0; n1 < 16; n1++) v[n1] = __half22float2(chp[16 * n1 + t]);
    dft16<false>(v);
    __syncthreads();                               // tw + weights ready
#pragma unroll
    for (int k1 = 0; k1 < 16; k1++){
        float2 bv = v[SLOT(k1)];
        if (k1) bv = cmul(bv, tw[t * k1]);
        buf[f * 272 + k1 * 17 + t] = bv;           // T write
    }
    __syncthreads();
#pragma unroll
    for (int n2 = 0; n2 < 16; n2++) v[n2] = buf[f * 272 + t * 17 + n2];  // T read
    __syncthreads();                               // T dead -> reuse as A
    dft16<false>(v);
#pragma unroll
    for (int k2 = 0; k2 < 16; k2++)
        buf[f * 257 + t + 16 * k2] = v[SLOT(k2)];  // A write
    __syncthreads();

    // ---- MLP: one thread per h-bin, packed half2 complex GEMV ----
    {
        __half2 xp[16];
#pragma unroll
        for (int i = 0; i < 16; i++){
            float2 q = buf[i * 257 + tid];         // A read (column tid)
            xp[i] = __floats2half2_rn(q.x, q.y);
        }
        __half2 o1p[16];
#pragma unroll
        for (int o = 0; o < 16; o++){
            __half2 Aa = __floats2half2_rn(0.f, 0.f);
            __half2 Bb = Aa;
#pragma unroll
            for (int i = 0; i < 16; i++){
                uint2 u = w1h[i * 16 + o];
                Aa = __hfma2(xp[i], *(__half2*)&u.x, Aa);
                Bb = __hfma2(xp[i], *(__half2*)&u.y, Bb);
            }
            float2 af = __half22float2(Aa), bf = __half22float2(Bb);
            float re = fmaxf(af.x - bf.y + b1c[o].x, 0.f);
            float im = fmaxf(af.y + bf.x + b1c[o].y, 0.f);
            o1p[o] = __floats2half2_rn(re, im);
        }
#pragma unroll
        for (int o = 0; o < 16; o++){
            __half2 Aa = __floats2half2_rn(0.f, 0.f);
            __half2 Bb = Aa;
#pragma unroll
            for (int i = 0; i < 16; i++){
                uint2 u = w2h[i * 16 + o];
                Aa = __hfma2(o1p[i], *(__half2*)&u.x, Aa);
                Bb = __hfma2(o1p[i], *(__half2*)&u.y, Bb);
            }
            float2 af = __half22float2(Aa), bf = __half22float2(Bb);
            const float ar = af.x - bf.y + b2c[o].x;
            const float ai = af.y + bf.x + b2c[o].y;
            const float sr = copysignf(fmaxf(fabsf(ar) - 0.01f, 0.f), ar);
            const float si = copysignf(fmaxf(fabsf(ai) - 0.01f, 0.f), ai);
            float2 q = buf[o * 257 + tid];         // original x (re-read)
            buf[o * 257 + tid] = make_float2(sr * q.x - si * q.y,
                                             sr * q.y + si * q.x);  // A write
        }
    }
    __syncthreads();

    // ---- inverse column FFT (bin-strided in, coalesced time-domain out) ----
#pragma unroll
    for (int k2 = 0; k2 < 16; k2++) v[k2] = buf[f * 257 + t + 16 * k2];  // A read
    __syncthreads();                               // A dead -> reuse as T
    dft16<true>(v);
#pragma unroll
    for (int m2 = 0; m2 < 16; m2++){
        float2 q = v[SLOT(m2)];
        if (m2) q = cmulc(q, tw[m2 * t]);
        buf[f * 272 + m2 * 17 + t] = q;            // T write
    }
    __syncthreads();
#pragma unroll
    for (int n = 0; n < 16; n++) v[n] = buf[f * 272 + t * 17 + n];       // T read
    dft16<true>(v);
#pragma unroll
    for (int m1 = 0; m1 < 16; m1++)
        chp[16 * m1 + t] = __floats2half2_rn(v[SLOT(m1)].x, v[SLOT(m1)].y);
}

// ---------------------------------------------------------------------------
// K3: row irfft. CTA = 32 rows of one (b,c) image, 2 rows packed per inverse
// complex FFT. Hermitian extension + edge-bin imag zeroing == irfft semantics.
// Scale 1/256, add residual.
// ---------------------------------------------------------------------------
__global__ void __launch_bounds__(256) k_rowifft(const float* __restrict__ x,
                                                 float* __restrict__ out){
    extern __shared__ char smraw[];
    float2* sbuf = (float2*)smraw;                 // 4352 f2
    float2* tw   = (float2*)(smraw + 34816);       // 256 f2

    const int tid = threadIdx.x;
    const int f = tid >> 4, t = tid & 15;
    const int bc = blockIdx.x >> 3;
    const int h0 = (blockIdx.x & 7) << 5;

    build_tw(tw, tid);

    const __half2* gsrc = g_buf + (size_t)bc * WF * HDIM;
    // Build packed full spectrum Z[f][0..255], Z = X0 + i*X1
    for (int e = tid; e < WF * 16; e += 256){
        const int wf = e >> 4, fp = e & 15;
        uint2 u = *(const uint2*)(gsrc + (size_t)wf * HDIM + h0 + 2 * fp);
        float2 a = __half22float2(*(__half2*)&u.x);
        float2 bq = __half22float2(*(__half2*)&u.y);
        float ay = a.y, by = bq.y;
        if (wf == 0 || wf == 128){ ay = 0.f; by = 0.f; }   // irfft ignores edge imag
        sbuf[fp * 257 + wf] = make_float2(a.x - by, ay + bq.x);
        if (wf >= 1 && wf <= 127)
            sbuf[fp * 257 + 256 - wf] = make_float2(a.x + by, bq.x - ay);
    }
    __syncthreads();

    float2 v[16];
#pragma unroll
    for (int k2 = 0; k2 < 16; k2++) v[k2] = sbuf[f * 257 + t + 16 * k2];
    __syncthreads();                               // S reads done before T writes
    dft16<true>(v);
#pragma unroll
    for (int m2 = 0; m2 < 16; m2++){
        float2 q = v[SLOT(m2)];
        if (m2) q = cmulc(q, tw[m2 * t]);
        sbuf[f * 272 + m2 * 17 + t] = q;
    }
    __syncthreads();
#pragma unroll
    for (int n = 0; n < 16; n++) v[n] = sbuf[f * 272 + t * 17 + n];
    dft16<true>(v);

    const float* bias0 = x   + ((size_t)bc * HDIM + h0 + 2 * f) * WDIM;
    float*       o0    = out + ((size_t)bc * HDIM + h0 + 2 * f) * WDIM;
#pragma unroll
    for (int m1 = 0; m1 < 16; m1++){
        float2 z = v[SLOT(m1)];
        const int w_ = 16 * m1 + t;
        o0[w_]        = z.x * (1.f / 256.f) + bias0[w_];
        o0[WDIM + w_] = z.y * (1.f / 256.f) + bias0[WDIM + w_];
    }
}

extern "C" void kernel_launch(void* const* d_in, const int* in_sizes, int n_in,
                              void* d_out, int out_size) {
    const float* x  = (const float*)d_in[0];
    const float* w1 = (const float*)d_in[1];
    const float* b1 = (const float*)d_in[2];
    const float* w2 = (const float*)d_in[3];
    const float* b2 = (const float*)d_in[4];
    float* out = (float*)d_out;

    const int SMEM_ROW = 34816 + 2048;             // 36864
    const int SMEM_COL = 41216;

    cudaFuncSetAttribute(k_rowfft,     cudaFuncAttributeMaxDynamicSharedMemorySize, SMEM_ROW);
    cudaFuncSetAttribute(k_colfft_mlp, cudaFuncAttributeMaxDynamicSharedMemorySize, SMEM_COL);
    cudaFuncSetAttribute(k_rowifft,    cudaFuncAttributeMaxDynamicSharedMemorySize, SMEM_ROW);

    k_rowfft<<<BSZ * CSZ * (HDIM / 32), 256, SMEM_ROW>>>(x);
    k_colfft_mlp<<<BSZ * NBLK * WF, 256, SMEM_COL>>>(w1, b1, w2, b2);
    k_rowifft<<<BSZ * CSZ * (HDIM / 32), 256, SMEM_ROW>>>(x, out);
}

// round 7
// speedup vs baseline: 1.4684x; 1.0360x over previous
#include <cuda_runtime.h>
#include <cuda_fp16.h>
#include <math.h>

#define HDIM 256
#define WDIM 256
#define WF   129
#define BSZ  4
#define CSZ  128
#define NBLK 8

// scratch spectrum buffer, layout [b, c, wf, h] as half2 (~67 MB)
__device__ __half2 g_buf[(size_t)BSZ * CSZ * WF * HDIM];

__device__ __forceinline__ float2 cadd(float2 a, float2 b){ return make_float2(a.x+b.x, a.y+b.y); }
__device__ __forceinline__ float2 csub(float2 a, float2 b){ return make_float2(a.x-b.x, a.y-b.y); }
__device__ __forceinline__ float2 cmul(float2 a, float2 b){
    return make_float2(a.x*b.x - a.y*b.y, a.x*b.y + a.y*b.x);
}
__device__ __forceinline__ float2 cmulc(float2 a, float2 b){  // a * conj(b)
    return make_float2(a.x*b.x + a.y*b.y, a.y*b.x - a.x*b.y);
}

// multiply by (-i) forward, (+i) inverse
template<bool INV>
__device__ __forceinline__ float2 mul_i(float2 a){
    return INV ? make_float2(-a.y, a.x) : make_float2(a.y, -a.x);
}

template<bool INV>
__device__ __forceinline__ void bf4(float2& x0, float2& x1, float2& x2, float2& x3){
    float2 t0 = cadd(x0, x2), t1 = csub(x0, x2);
    float2 t2 = cadd(x1, x3), t3 = csub(x1, x3);
    float2 j3 = mul_i<INV>(t3);
    x0 = cadd(t0, t2);
    x2 = csub(t0, t2);
    x1 = cadd(t1, j3);
    x3 = csub(t1, j3);
}

// In-register 16-point DFT (radix-4 x radix-4), fp32. Input natural order.
// Output: bin k = c + 4d lands in slot 4c + d  (slot(k) = ((k&3)<<2)|(k>>2)).
template<bool INV>
__device__ __forceinline__ void dft16(float2 v[16]){
    const float S = INV ? 1.f : -1.f;
    const float2 W1 = make_float2( 0.92387953251128674f, S*0.38268343236508978f);
    const float2 W2 = make_float2( 0.70710678118654752f, S*0.70710678118654752f);
    const float2 W3 = make_float2( 0.38268343236508978f, S*0.92387953251128674f);
    const float2 W6 = make_float2(-0.70710678118654752f, S*0.70710678118654752f);
    const float2 W9 = make_float2(-0.92387953251128674f, -S*0.38268343236508978f);

    bf4<INV>(v[0], v[4], v[8],  v[12]);
    bf4<INV>(v[1], v[5], v[9],  v[13]);
    bf4<INV>(v[2], v[6], v[10], v[14]);
    bf4<INV>(v[3], v[7], v[11], v[15]);
    v[5]  = cmul(v[5],  W1);
    v[9]  = cmul(v[9],  W2);
    v[13] = cmul(v[13], W3);
    v[6]  = cmul(v[6],  W2);
    v[10] = mul_i<INV>(v[10]);
    v[14] = cmul(v[14], W6);
    v[7]  = cmul(v[7],  W3);
    v[11] = cmul(v[11], W6);
    v[15] = cmul(v[15], W9);
    bf4<INV>(v[0],  v[1],  v[2],  v[3]);
    bf4<INV>(v[4],  v[5],  v[6],  v[7]);
    bf4<INV>(v[8],  v[9],  v[10], v[11]);
    bf4<INV>(v[12], v[13], v[14], v[15]);
}

// ---------------- packed half2 complex kernels ----------------
__device__ __forceinline__ __half2 hswap(__half2 a){ return __lowhigh2highlow(a); }

template<bool INV>
__device__ __forceinline__ __half2 mul_i_h(__half2 a){
    const __half2 sp = __floats2half2_rn(INV ? -1.f : 1.f, INV ? 1.f : -1.f);
    return __hmul2(hswap(a), sp);
}

template<bool INV>
__device__ __forceinline__ void bf4h(__half2& x0, __half2& x1, __half2& x2, __half2& x3){
    __half2 t0 = __hadd2(x0, x2), t1 = __hsub2(x0, x2);
    __half2 t2 = __hadd2(x1, x3), t3 = __hsub2(x1, x3);
    __half2 s3 = hswap(t3);
    const __half2 sp = __floats2half2_rn(INV ? -1.f : 1.f, INV ? 1.f : -1.f);
    const __half2 sn = __floats2half2_rn(INV ? 1.f : -1.f, INV ? -1.f : 1.f);
    x0 = __hadd2(t0, t2);
    x2 = __hsub2(t0, t2);
    x1 = __hfma2(s3, sp, t1);
    x3 = __hfma2(s3, sn, t1);
}

// v * (wr + i*wi_s): wi_s carries the direction sign already
__device__ __forceinline__ __half2 cmulh_c(__half2 v, float wr, float wi_s){
    __half2 wrr = __floats2half2_rn(wr, wr);
    __half2 wni = __floats2half2_rn(-wi_s, wi_s);
    return __hfma2(hswap(v), wni, __hmul2(v, wrr));
}

// v * twiddle from packed table entry (u.x = (c,c), u.y = (-s,s) or (s,-s))
__device__ __forceinline__ __half2 cmulh_t(__half2 v, uint2 u){
    return __hfma2(hswap(v), *(__half2*)&u.y, __hmul2(v, *(__half2*)&u.x));
}

template<bool INV>
__device__ __forceinline__ void dft16h(__half2 v[16]){
    const float S = INV ? 1.f : -1.f;
    bf4h<INV>(v[0], v[4], v[8],  v[12]);
    bf4h<INV>(v[1], v[5], v[9],  v[13]);
    bf4h<INV>(v[2], v[6], v[10], v[14]);
    bf4h<INV>(v[3], v[7], v[11], v[15]);
    v[5]  = cmulh_c(v[5],   0.92387953f, S*0.38268343f);
    v[9]  = cmulh_c(v[9],   0.70710678f, S*0.70710678f);
    v[13] = cmulh_c(v[13],  0.38268343f, S*0.92387953f);
    v[6]  = cmulh_c(v[6],   0.70710678f, S*0.70710678f);
    v[10] = mul_i_h<INV>(v[10]);
    v[14] = cmulh_c(v[14], -0.70710678f, S*0.70710678f);
    v[7]  = cmulh_c(v[7],   0.38268343f, S*0.92387953f);
    v[11] = cmulh_c(v[11], -0.70710678f, S*0.70710678f);
    v[15] = cmulh_c(v[15], -0.92387953f, -S*0.38268343f);
    bf4h<INV>(v[0],  v[1],  v[2],  v[3]);
    bf4h<INV>(v[4],  v[5],  v[6],  v[7]);
    bf4h<INV>(v[8],  v[9],  v[10], v[11]);
    bf4h<INV>(v[12], v[13], v[14], v[15]);
}

#define SLOT(k) ((((k) & 3) << 2) | ((k) >> 2))

__device__ __forceinline__ void build_tw(float2* tw, int tid){
    float s, c;
    sincosf((float)tid * (-6.283185307179586f / 256.f), &s, &c);
    tw[tid] = make_float2(c, s);
}

// ---------------------------------------------------------------------------
// K1: row rfft (fp32 FFT). CTA = 32 rows, 2 real rows packed per complex FFT.
// Output transposed [b,c,wf,h] half2, scaled 1/256.
// ---------------------------------------------------------------------------
__global__ void __launch_bounds__(256) k_rowfft(const float* __restrict__ x){
    extern __shared__ char smraw[];
    float2* sbuf = (float2*)smraw;                 // 4352 float2
    float2* tw   = (float2*)(smraw + 34816);       // 256 float2

    const int tid = threadIdx.x;
    const int f = tid >> 4, t = tid & 15;
    const int bc = blockIdx.x >> 3;
    const int h0 = (blockIdx.x & 7) << 5;

    build_tw(tw, tid);

    const float* r0 = x + ((size_t)bc * HDIM + h0 + 2 * f) * WDIM;
    float2 v[16];
#pragma unroll
    for (int n1 = 0; n1 < 16; n1++)
        v[n1] = make_float2(r0[16 * n1 + t], r0[WDIM + 16 * n1 + t]);
    dft16<false>(v);
    __syncthreads();

#pragma unroll
    for (int k1 = 0; k1 < 16; k1++){
        float2 bv = v[SLOT(k1)];
        if (k1) bv = cmul(bv, tw[t * k1]);
        sbuf[f * 272 + k1 * 17 + t] = bv;
    }
    __syncthreads();
#pragma unroll
    for (int n2 = 0; n2 < 16; n2++)
        v[n2] = sbuf[f * 272 + t * 17 + n2];
    __syncthreads();
    dft16<false>(v);
#pragma unroll
    for (int k2 = 0; k2 < 16; k2++)
        sbuf[f * 257 + t + 16 * k2] = v[SLOT(k2)];
    __syncthreads();

    __half2* dst = g_buf + (size_t)bc * WF * HDIM;
    for (int e = tid; e < WF * 32; e += 256){
        const int wf = e >> 5, r = e & 31, fp = r >> 1;
        float2 Z1 = sbuf[fp * 257 + wf];
        float2 Z2 = sbuf[fp * 257 + ((256 - wf) & 255)];
        float2 val = (r & 1)
            ? make_float2((Z1.y + Z2.y) * 0.5f, (Z2.x - Z1.x) * 0.5f)
            : make_float2((Z1.x + Z2.x) * 0.5f, (Z1.y - Z2.y) * 0.5f);
        dst[(size_t)wf * HDIM + h0 + r] =
            __floats2half2_rn(val.x * (1.f / 256.f), val.y * (1.f / 256.f));
    }
}

// ---------------------------------------------------------------------------
// K2: fully packed-fp16 column FFT + block MLP + inverse FFT, in-place g_buf.
// Complex = half2(re,im). Th (stride 272) and Ah (stride 257) alias one buffer.
// ---------------------------------------------------------------------------
__global__ void __launch_bounds__(256) k_colfft_mlp(
        const float* __restrict__ w1g, const float* __restrict__ b1g,
        const float* __restrict__ w2g, const float* __restrict__ b2g){
    extern __shared__ char smraw[];
    __half2* bufh = (__half2*)smraw;               // 4352 h2  [0, 17408)
    uint2*   twf  = (uint2*)(smraw + 17408);       // 256 u2   [17408, 19456)
    uint2*   twi  = (uint2*)(smraw + 19456);       // 256 u2   [19456, 21504)
    uint2*   w1h  = (uint2*)(smraw + 21504);       // 256 u2   [21504, 23552)
    uint2*   w2h  = (uint2*)(smraw + 23552);       // 256 u2   [23552, 25600)
    float2*  b1c  = (float2*)(smraw + 25600);      // 16 f2
    float2*  b2c  = (float2*)(smraw + 25728);      // 16 f2    end 25856

    const int tid = threadIdx.x;
    const int f = tid >> 4, t = tid & 15;
    const int wf = blockIdx.x % WF;
    const int bk = blockIdx.x / WF;
    const int k = bk & 7, b = bk >> 3;

    {   // packed twiddle tables: fwd (c,c)(-s,s), inv (c,c)(s,-s) with s=sin(-θ)
        float s, c;
        sincosf((float)tid * (-6.283185307179586f / 256.f), &s, &c);
        __half2 cc = __floats2half2_rn(c, c);
        __half2 nf = __floats2half2_rn(-s, s);
        __half2 ni = __floats2half2_rn(s, -s);
        uint2 u;
        u.x = *(unsigned int*)&cc; u.y = *(unsigned int*)&nf; twf[tid] = u;
        u.y = *(unsigned int*)&ni; twi[tid] = u;
    }
    {   // weights [2][8][16][16], duplicate-packed
        float wr = w1g[k * 256 + tid], wi = w1g[2048 + k * 256 + tid];
        __half2 hr = __floats2half2_rn(wr, wr), hi = __floats2half2_rn(wi, wi);
        uint2 u;
        u.x = *(unsigned int*)&hr; u.y = *(unsigned int*)&hi; w1h[tid] = u;
        wr = w2g[k * 256 + tid]; wi = w2g[2048 + k * 256 + tid];
        hr = __floats2half2_rn(wr, wr); hi = __floats2half2_rn(wi, wi);
        u.x = *(unsigned int*)&hr; u.y = *(unsigned int*)&hi; w2h[tid] = u;
    }
    if (tid < 16){
        b1c[tid] = make_float2(b1g[k * 16 + tid], b1g[128 + k * 16 + tid]);
        b2c[tid] = make_float2(b2g[k * 16 + tid], b2g[128 + k * 16 + tid]);
    }

    __half2* chp = g_buf + ((size_t)(b * CSZ + k * 16 + f) * WF + wf) * HDIM;

    __half2 v[16];
#pragma unroll
    for (int n1 = 0; n1 < 16; n1++) v[n1] = chp[16 * n1 + t];
    dft16h<false>(v);
    __syncthreads();                               // tables ready
#pragma unroll
    for (int k1 = 0; k1 < 16; k1++){
        __half2 bv = v[SLOT(k1)];
        if (k1) bv = cmulh_t(bv, twf[t * k1]);
        bufh[f * 272 + k1 * 17 + t] = bv;          // T write
    }
    __syncthreads();
#pragma unroll
    for (int n2 = 0; n2 < 16; n2++) v[n2] = bufh[f * 272 + t * 17 + n2];  // T read
    __syncthreads();                               // T dead -> reuse as A
    dft16h<false>(v);
#pragma unroll
    for (int k2 = 0; k2 < 16; k2++)
        bufh[f * 257 + t + 16 * k2] = v[SLOT(k2)]; // A write
    __syncthreads();

    // ---- MLP: one thread per h-bin, packed half2 complex GEMV ----
    {
        __half2 xp[16];
#pragma unroll
        for (int i = 0; i < 16; i++) xp[i] = bufh[i * 257 + tid];
        __half2 o1p[16];
#pragma unroll
        for (int o = 0; o < 16; o++){
            __half2 Aa = __floats2half2_rn(0.f, 0.f);
            __half2 Bb = Aa;
#pragma unroll
            for (int i = 0; i < 16; i++){
                uint2 u = w1h[i * 16 + o];
                Aa = __hfma2(xp[i], *(__half2*)&u.x, Aa);
                Bb = __hfma2(xp[i], *(__half2*)&u.y, Bb);
            }
            float2 af = __half22float2(Aa), bf = __half22float2(Bb);
            float re = fmaxf(af.x - bf.y + b1c[o].x, 0.f);
            float im = fmaxf(af.y + bf.x + b1c[o].y, 0.f);
            o1p[o] = __floats2half2_rn(re, im);
        }
#pragma unroll
        for (int o = 0; o < 16; o++){
            __half2 Aa = __floats2half2_rn(0.f, 0.f);
            __half2 Bb = Aa;
#pragma unroll
            for (int i = 0; i < 16; i++){
                uint2 u = w2h[i * 16 + o];
                Aa = __hfma2(o1p[i], *(__half2*)&u.x, Aa);
                Bb = __hfma2(o1p[i], *(__half2*)&u.y, Bb);
            }
            float2 af = __half22float2(Aa), bf = __half22float2(Bb);
            const float ar = af.x - bf.y + b2c[o].x;
            const float ai = af.y + bf.x + b2c[o].y;
            const float sr = copysignf(fmaxf(fabsf(ar) - 0.01f, 0.f), ar);
            const float si = copysignf(fmaxf(fabsf(ai) - 0.01f, 0.f), ai);
            float2 q = __half22float2(xp[o]);
            bufh[o * 257 + tid] = __floats2half2_rn(sr * q.x - si * q.y,
                                                    sr * q.y + si * q.x);
        }
    }
    __syncthreads();

    // ---- inverse column FFT (bin-strided in, coalesced time-domain out) ----
#pragma unroll
    for (int k2 = 0; k2 < 16; k2++) v[k2] = bufh[f * 257 + t + 16 * k2];  // A read
    __syncthreads();                               // A dead -> reuse as T
    dft16h<true>(v);
#pragma unroll
    for (int m2 = 0; m2 < 16; m2++){
        __half2 q = v[SLOT(m2)];
        if (m2) q = cmulh_t(q, twi[m2 * t]);
        bufh[f * 272 + m2 * 17 + t] = q;           // T write
    }
    __syncthreads();
#pragma unroll
    for (int n = 0; n < 16; n++) v[n] = bufh[f * 272 + t * 17 + n];       // T read
    dft16h<true>(v);
#pragma unroll
    for (int m1 = 0; m1 < 16; m1++)
        chp[16 * m1 + t] = v[SLOT(m1)];
}

// ---------------------------------------------------------------------------
// K3: row irfft (fp32 FFT). Hermitian extension + edge-bin imag zeroing ==
// irfft semantics. Scale 1/256, add residual.
// ---------------------------------------------------------------------------
__global__ void __launch_bounds__(256) k_rowifft(const float* __restrict__ x,
                                                 float* __restrict__ out){
    extern __shared__ char smraw[];
    float2* sbuf = (float2*)smraw;                 // 4352 f2
    float2* tw   = (float2*)(smraw + 34816);       // 256 f2

    const int tid = threadIdx.x;
    const int f = tid >> 4, t = tid & 15;
    const int bc = blockIdx.x >> 3;
    const int h0 = (blockIdx.x & 7) << 5;

    build_tw(tw, tid);

    const __half2* gsrc = g_buf + (size_t)bc * WF * HDIM;
    for (int e = tid; e < WF * 16; e += 256){
        const int wf = e >> 4, fp = e & 15;
        uint2 u = *(const uint2*)(gsrc + (size_t)wf * HDIM + h0 + 2 * fp);
        float2 a = __half22float2(*(__half2*)&u.x);
        float2 bq = __half22float2(*(__half2*)&u.y);
        float ay = a.y, by = bq.y;
        if (wf == 0 || wf == 128){ ay = 0.f; by = 0.f; }
        sbuf[fp * 257 + wf] = make_float2(a.x - by, ay + bq.x);
        if (wf >= 1 && wf <= 127)
            sbuf[fp * 257 + 256 - wf] = make_float2(a.x + by, bq.x - ay);
    }
    __syncthreads();

    float2 v[16];
#pragma unroll
    for (int k2 = 0; k2 < 16; k2++) v[k2] = sbuf[f * 257 + t + 16 * k2];
    __syncthreads();
    dft16<true>(v);
#pragma unroll
    for (int m2 = 0; m2 < 16; m2++){
        float2 q = v[SLOT(m2)];
        if (m2) q = cmulc(q, tw[m2 * t]);
        sbuf[f * 272 + m2 * 17 + t] = q;
    }
    __syncthreads();
#pragma unroll
    for (int n = 0; n < 16; n++) v[n] = sbuf[f * 272 + t * 17 + n];
    dft16<true>(v);

    const float* bias0 = x   + ((size_t)bc * HDIM + h0 + 2 * f) * WDIM;
    float*       o0    = out + ((size_t)bc * HDIM + h0 + 2 * f) * WDIM;
#pragma unroll
    for (int m1 = 0; m1 < 16; m1++){
        float2 z = v[SLOT(m1)];
        const int w_ = 16 * m1 + t;
        o0[w_]        = z.x * (1.f / 256.f) + bias0[w_];
        o0[WDIM + w_] = z.y * (1.f / 256.f) + bias0[WDIM + w_];
    }
}

extern "C" void kernel_launch(void* const* d_in, const int* in_sizes, int n_in,
                              void* d_out, int out_size) {
    const float* x  = (const float*)d_in[0];
    const float* w1 = (const float*)d_in[1];
    const float* b1 = (const float*)d_in[2];
    const float* w2 = (const float*)d_in[3];
    const float* b2 = (const float*)d_in[4];
    float* out = (float*)d_out;

    const int SMEM_ROW = 34816 + 2048;             // 36864
    const int SMEM_COL = 25856;

    cudaFuncSetAttribute(k_rowfft,     cudaFuncAttributeMaxDynamicSharedMemorySize, SMEM_ROW);
    cudaFuncSetAttribute(k_colfft_mlp, cudaFuncAttributeMaxDynamicSharedMemorySize, SMEM_COL);
    cudaFuncSetAttribute(k_rowifft,    cudaFuncAttributeMaxDynamicSharedMemorySize, SMEM_ROW);

    k_rowfft<<<BSZ * CSZ * (HDIM / 32), 256, SMEM_ROW>>>(x);
    k_colfft_mlp<<<BSZ * NBLK * WF, 256, SMEM_COL>>>(w1, b1, w2, b2);
    k_rowifft<<<BSZ * CSZ * (HDIM / 32), 256, SMEM_ROW>>>(x, out);
}

// round 8
// speedup vs baseline: 1.5815x; 1.0771x over previous
#include <cuda_runtime.h>
#include <cuda_fp16.h>
#include <math.h>

#define HDIM 256
#define WDIM 256
#define WF   129
#define BSZ  4
#define CSZ  128
#define NBLK 8

// scratch spectrum buffer, layout [b, c, wf, h] as half2 (~67 MB)
__device__ __half2 g_buf[(size_t)BSZ * CSZ * WF * HDIM];

// ---------------- packed half2 complex helpers ----------------
__device__ __forceinline__ __half2 hswap(__half2 a){ return __lowhigh2highlow(a); }

template<bool INV>
__device__ __forceinline__ __half2 mul_i_h(__half2 a){
    const __half2 sp = __floats2half2_rn(INV ? -1.f : 1.f, INV ? 1.f : -1.f);
    return __hmul2(hswap(a), sp);
}

template<bool INV>
__device__ __forceinline__ void bf4h(__half2& x0, __half2& x1, __half2& x2, __half2& x3){
    __half2 t0 = __hadd2(x0, x2), t1 = __hsub2(x0, x2);
    __half2 t2 = __hadd2(x1, x3), t3 = __hsub2(x1, x3);
    __half2 s3 = hswap(t3);
    const __half2 sp = __floats2half2_rn(INV ? -1.f : 1.f, INV ? 1.f : -1.f);
    const __half2 sn = __floats2half2_rn(INV ? 1.f : -1.f, INV ? -1.f : 1.f);
    x0 = __hadd2(t0, t2);
    x2 = __hsub2(t0, t2);
    x1 = __hfma2(s3, sp, t1);
    x3 = __hfma2(s3, sn, t1);
}

// v * (wr + i*wi_s): wi_s carries direction sign
__device__ __forceinline__ __half2 cmulh_c(__half2 v, float wr, float wi_s){
    __half2 wrr = __floats2half2_rn(wr, wr);
    __half2 wni = __floats2half2_rn(-wi_s, wi_s);
    return __hfma2(hswap(v), wni, __hmul2(v, wrr));
}

// v * twiddle from packed table entry (u.x = (c,c), u.y = (-s,s) or (s,-s))
__device__ __forceinline__ __half2 cmulh_t(__half2 v, uint2 u){
    return __hfma2(hswap(v), *(__half2*)&u.y, __hmul2(v, *(__half2*)&u.x));
}

// In-register fp16 16-point DFT (radix-4^2). Bin k lands in SLOT(k).
template<bool INV>
__device__ __forceinline__ void dft16h(__half2 v[16]){
    const float S = INV ? 1.f : -1.f;
    bf4h<INV>(v[0], v[4], v[8],  v[12]);
    bf4h<INV>(v[1], v[5], v[9],  v[13]);
    bf4h<INV>(v[2], v[6], v[10], v[14]);
    bf4h<INV>(v[3], v[7], v[11], v[15]);
    v[5]  = cmulh_c(v[5],   0.92387953f, S*0.38268343f);
    v[9]  = cmulh_c(v[9],   0.70710678f, S*0.70710678f);
    v[13] = cmulh_c(v[13],  0.38268343f, S*0.92387953f);
    v[6]  = cmulh_c(v[6],   0.70710678f, S*0.70710678f);
    v[10] = mul_i_h<INV>(v[10]);
    v[14] = cmulh_c(v[14], -0.70710678f, S*0.70710678f);
    v[7]  = cmulh_c(v[7],   0.38268343f, S*0.92387953f);
    v[11] = cmulh_c(v[11], -0.70710678f, S*0.70710678f);
    v[15] = cmulh_c(v[15], -0.92387953f, -S*0.38268343f);
    bf4h<INV>(v[0],  v[1],  v[2],  v[3]);
    bf4h<INV>(v[4],  v[5],  v[6],  v[7]);
    bf4h<INV>(v[8],  v[9],  v[10], v[11]);
    bf4h<INV>(v[12], v[13], v[14], v[15]);
}

#define SLOT(k) ((((k) & 3) << 2) | ((k) >> 2))

// packed fp16 twiddle: u.x = (c,c), u.y = fwd ? (-s,s) : (s,-s), s = sin(-2πk/256)
__device__ __forceinline__ void build_twh(uint2* twf, uint2* twi, int tid){
    float s, c;
    sincosf((float)tid * (-6.283185307179586f / 256.f), &s, &c);
    __half2 cc = __floats2half2_rn(c, c);
    __half2 nf = __floats2half2_rn(-s, s);
    __half2 ni = __floats2half2_rn(s, -s);
    uint2 u;
    u.x = *(unsigned int*)&cc;
    if (twf){ u.y = *(unsigned int*)&nf; twf[tid] = u; }
    if (twi){ u.y = *(unsigned int*)&ni; twi[tid] = u; }
}

// ---------------------------------------------------------------------------
// K1: row rfft, fp16 FFT. CTA = 32 rows, 2 real rows packed per complex FFT.
// Output transposed [b,c,wf,h] half2, scaled 1/256 (split math in fp32).
// ---------------------------------------------------------------------------
__global__ void __launch_bounds__(256) k_rowfft(const float* __restrict__ x){
    extern __shared__ char smraw[];
    __half2* bufh = (__half2*)smraw;               // 4352 h2  [0, 17408)
    uint2*   twf  = (uint2*)(smraw + 17408);       // 256 u2   [17408, 19456)

    const int tid = threadIdx.x;
    const int f = tid >> 4, t = tid & 15;
    const int bc = blockIdx.x >> 3;
    const int h0 = (blockIdx.x & 7) << 5;

    build_twh(twf, nullptr, tid);

    const float* r0 = x + ((size_t)bc * HDIM + h0 + 2 * f) * WDIM;
    __half2 v[16];
#pragma unroll
    for (int n1 = 0; n1 < 16; n1++)
        v[n1] = __floats2half2_rn(r0[16 * n1 + t], r0[WDIM + 16 * n1 + t]);
    dft16h<false>(v);
    __syncthreads();                               // twf ready

#pragma unroll
    for (int k1 = 0; k1 < 16; k1++){
        __half2 bv = v[SLOT(k1)];
        if (k1) bv = cmulh_t(bv, twf[t * k1]);
        bufh[f * 272 + k1 * 17 + t] = bv;          // T write
    }
    __syncthreads();
#pragma unroll
    for (int n2 = 0; n2 < 16; n2++)
        v[n2] = bufh[f * 272 + t * 17 + n2];       // T read
    __syncthreads();                               // T dead -> S
    dft16h<false>(v);
#pragma unroll
    for (int k2 = 0; k2 < 16; k2++)
        bufh[f * 257 + t + 16 * k2] = v[SLOT(k2)]; // S write
    __syncthreads();

    __half2* dst = g_buf + (size_t)bc * WF * HDIM;
    for (int e = tid; e < WF * 32; e += 256){
        const int wf = e >> 5, r = e & 31, fp = r >> 1;
        float2 Z1 = __half22float2(bufh[fp * 257 + wf]);
        float2 Z2 = __half22float2(bufh[fp * 257 + ((256 - wf) & 255)]);
        float2 val = (r & 1)
            ? make_float2((Z1.y + Z2.y) * 0.5f, (Z2.x - Z1.x) * 0.5f)
            : make_float2((Z1.x + Z2.x) * 0.5f, (Z1.y - Z2.y) * 0.5f);
        dst[(size_t)wf * HDIM + h0 + r] =
            __floats2half2_rn(val.x * (1.f / 256.f), val.y * (1.f / 256.f));
    }
}

// ---------------------------------------------------------------------------
// K2: packed-fp16 column FFT + block MLP + inverse FFT, in-place g_buf.
// Weights packed as uint4 = 2 output channels per LDS.128.
// ---------------------------------------------------------------------------
__global__ void __launch_bounds__(256) k_colfft_mlp(
        const float* __restrict__ w1g, const float* __restrict__ b1g,
        const float* __restrict__ w2g, const float* __restrict__ b2g){
    extern __shared__ char smraw[];
    __half2* bufh = (__half2*)smraw;               // 4352 h2  [0, 17408)
    uint2*   twf  = (uint2*)(smraw + 17408);       // 256 u2   [17408, 19456)
    uint2*   twi  = (uint2*)(smraw + 19456);       // 256 u2   [19456, 21504)
    uint4*   w1q  = (uint4*)(smraw + 21504);       // 128 u4   [21504, 23552)
    uint4*   w2q  = (uint4*)(smraw + 23552);       // 128 u4   [23552, 25600)
    float2*  b1c  = (float2*)(smraw + 25600);      // 16 f2
    float2*  b2c  = (float2*)(smraw + 25728);      // 16 f2    end 25856

    const int tid = threadIdx.x;
    const int f = tid >> 4, t = tid & 15;
    const int wf = blockIdx.x % WF;
    const int bk = blockIdx.x / WF;
    const int k = bk & 7, b = bk >> 3;

    build_twh(twf, twi, tid);
    if (tid < 128){   // weights [2][8][16][16]: pack (o, o+1) per uint4
        const int i = tid >> 3, o2 = tid & 7, o = o2 << 1;
        float wr0 = w1g[k * 256 + i * 16 + o];
        float wi0 = w1g[2048 + k * 256 + i * 16 + o];
        float wr1 = w1g[k * 256 + i * 16 + o + 1];
        float wi1 = w1g[2048 + k * 256 + i * 16 + o + 1];
        __half2 h0_ = __floats2half2_rn(wr0, wr0), h1_ = __floats2half2_rn(wi0, wi0);
        __half2 h2_ = __floats2half2_rn(wr1, wr1), h3_ = __floats2half2_rn(wi1, wi1);
        uint4 u;
        u.x = *(unsigned int*)&h0_; u.y = *(unsigned int*)&h1_;
        u.z = *(unsigned int*)&h2_; u.w = *(unsigned int*)&h3_;
        w1q[i * 8 + o2] = u;
        wr0 = w2g[k * 256 + i * 16 + o];
        wi0 = w2g[2048 + k * 256 + i * 16 + o];
        wr1 = w2g[k * 256 + i * 16 + o + 1];
        wi1 = w2g[2048 + k * 256 + i * 16 + o + 1];
        h0_ = __floats2half2_rn(wr0, wr0); h1_ = __floats2half2_rn(wi0, wi0);
        h2_ = __floats2half2_rn(wr1, wr1); h3_ = __floats2half2_rn(wi1, wi1);
        u.x = *(unsigned int*)&h0_; u.y = *(unsigned int*)&h1_;
        u.z = *(unsigned int*)&h2_; u.w = *(unsigned int*)&h3_;
        w2q[i * 8 + o2] = u;
    }
    if (tid < 16){
        b1c[tid] = make_float2(b1g[k * 16 + tid], b1g[128 + k * 16 + tid]);
        b2c[tid] = make_float2(b2g[k * 16 + tid], b2g[128 + k * 16 + tid]);
    }

    __half2* chp = g_buf + ((size_t)(b * CSZ + k * 16 + f) * WF + wf) * HDIM;

    __half2 v[16];
#pragma unroll
    for (int n1 = 0; n1 < 16; n1++) v[n1] = chp[16 * n1 + t];
    dft16h<false>(v);
    __syncthreads();                               // tables ready
#pragma unroll
    for (int k1 = 0; k1 < 16; k1++){
        __half2 bv = v[SLOT(k1)];
        if (k1) bv = cmulh_t(bv, twf[t * k1]);
        bufh[f * 272 + k1 * 17 + t] = bv;          // T write
    }
    __syncthreads();
#pragma unroll
    for (int n2 = 0; n2 < 16; n2++) v[n2] = bufh[f * 272 + t * 17 + n2];  // T read
    __syncthreads();                               // T dead -> A
    dft16h<false>(v);
#pragma unroll
    for (int k2 = 0; k2 < 16; k2++)
        bufh[f * 257 + t + 16 * k2] = v[SLOT(k2)]; // A write
    __syncthreads();

    // ---- MLP: one thread per h-bin, 2 output channels per weight LDS.128 ----
    {
        __half2 xp[16];
#pragma unroll
        for (int i = 0; i < 16; i++) xp[i] = bufh[i * 257 + tid];
        __half2 o1p[16];
#pragma unroll
        for (int o2 = 0; o2 < 8; o2++){
            __half2 A0 = __floats2half2_rn(0.f, 0.f);
            __half2 B0 = A0, A1 = A0, B1 = A0;
#pragma unroll
            for (int i = 0; i < 16; i++){
                uint4 u = w1q[i * 8 + o2];
                A0 = __hfma2(xp[i], *(__half2*)&u.x, A0);
                B0 = __hfma2(xp[i], *(__half2*)&u.y, B0);
                A1 = __hfma2(xp[i], *(__half2*)&u.z, A1);
                B1 = __hfma2(xp[i], *(__half2*)&u.w, B1);
            }
            float2 af = __half22float2(A0), bf = __half22float2(B0);
            o1p[2*o2] = __floats2half2_rn(
                fmaxf(af.x - bf.y + b1c[2*o2].x, 0.f),
                fmaxf(af.y + bf.x + b1c[2*o2].y, 0.f));
            af = __half22float2(A1); bf = __half22float2(B1);
            o1p[2*o2+1] = __floats2half2_rn(
                fmaxf(af.x - bf.y + b1c[2*o2+1].x, 0.f),
                fmaxf(af.y + bf.x + b1c[2*o2+1].y, 0.f));
        }
#pragma unroll
        for (int o2 = 0; o2 < 8; o2++){
            __half2 A0 = __floats2half2_rn(0.f, 0.f);
            __half2 B0 = A0, A1 = A0, B1 = A0;
#pragma unroll
            for (int i = 0; i < 16; i++){
                uint4 u = w2q[i * 8 + o2];
                A0 = __hfma2(o1p[i], *(__half2*)&u.x, A0);
                B0 = __hfma2(o1p[i], *(__half2*)&u.y, B0);
                A1 = __hfma2(o1p[i], *(__half2*)&u.z, A1);
                B1 = __hfma2(o1p[i], *(__half2*)&u.w, B1);
            }
#pragma unroll
            for (int half_ = 0; half_ < 2; half_++){
                const int o = 2*o2 + half_;
                float2 af = __half22float2(half_ ? A1 : A0);
                float2 bf = __half22float2(half_ ? B1 : B0);
                const float ar = af.x - bf.y + b2c[o].x;
                const float ai = af.y + bf.x + b2c[o].y;
                const float sr = copysignf(fmaxf(fabsf(ar) - 0.01f, 0.f), ar);
                const float si = copysignf(fmaxf(fabsf(ai) - 0.01f, 0.f), ai);
                float2 q = __half22float2(xp[o]);
                bufh[o * 257 + tid] = __floats2half2_rn(sr * q.x - si * q.y,
                                                        sr * q.y + si * q.x);
            }
        }
    }
    __syncthreads();

    // ---- inverse column FFT ----
#pragma unroll
    for (int k2 = 0; k2 < 16; k2++) v[k2] = bufh[f * 257 + t + 16 * k2];  // A read
    __syncthreads();                               // A dead -> T
    dft16h<true>(v);
#pragma unroll
    for (int m2 = 0; m2 < 16; m2++){
        __half2 q = v[SLOT(m2)];
        if (m2) q = cmulh_t(q, twi[m2 * t]);
        bufh[f * 272 + m2 * 17 + t] = q;           // T write
    }
    __syncthreads();
#pragma unroll
    for (int n = 0; n < 16; n++) v[n] = bufh[f * 272 + t * 17 + n];       // T read
    dft16h<true>(v);
#pragma unroll
    for (int m1 = 0; m1 < 16; m1++)
        chp[16 * m1 + t] = v[SLOT(m1)];
}

// ---------------------------------------------------------------------------
// K3: row irfft, fp16 FFT. Hermitian extension + edge-bin imag zeroing ==
// irfft semantics. Scale 1/256 + residual in fp32.
// ---------------------------------------------------------------------------
__global__ void __launch_bounds__(256) k_rowifft(const float* __restrict__ x,
                                                 float* __restrict__ out){
    extern __shared__ char smraw[];
    __half2* bufh = (__half2*)smraw;               // 4352 h2  [0, 17408)
    uint2*   twi  = (uint2*)(smraw + 17408);       // 256 u2   [17408, 19456)

    const int tid = threadIdx.x;
    const int f = tid >> 4, t = tid & 15;
    const int bc = blockIdx.x >> 3;
    const int h0 = (blockIdx.x & 7) << 5;

    build_twh(nullptr, twi, tid);

    const __half2* gsrc = g_buf + (size_t)bc * WF * HDIM;
    // Build packed full spectrum Z[fp][0..255], Z = X_{2fp} + i*X_{2fp+1}
    for (int e = tid; e < WF * 16; e += 256){
        const int wf = e >> 4, fp = e & 15;
        uint2 u = *(const uint2*)(gsrc + (size_t)wf * HDIM + h0 + 2 * fp);
        float2 a  = __half22float2(*(__half2*)&u.x);
        float2 bq = __half22float2(*(__half2*)&u.y);
        float ay = a.y, by = bq.y;
        if (wf == 0 || wf == 128){ ay = 0.f; by = 0.f; }
        bufh[fp * 257 + wf] = __floats2half2_rn(a.x - by, ay + bq.x);
        if (wf >= 1 && wf <= 127)
            bufh[fp * 257 + 256 - wf] = __floats2half2_rn(a.x + by, bq.x - ay);
    }
    __syncthreads();

    __half2 v[16];
#pragma unroll
    for (int k2 = 0; k2 < 16; k2++) v[k2] = bufh[f * 257 + t + 16 * k2];  // S read
    __syncthreads();                               // S dead -> T
    dft16h<true>(v);
#pragma unroll
    for (int m2 = 0; m2 < 16; m2++){
        __half2 q = v[SLOT(m2)];
        if (m2) q = cmulh_t(q, twi[m2 * t]);
        bufh[f * 272 + m2 * 17 + t] = q;           // T write
    }
    __syncthreads();
#pragma unroll
    for (int n = 0; n < 16; n++) v[n] = bufh[f * 272 + t * 17 + n];       // T read
    dft16h<true>(v);

    const float* bias0 = x   + ((size_t)bc * HDIM + h0 + 2 * f) * WDIM;
    float*       o0    = out + ((size_t)bc * HDIM + h0 + 2 * f) * WDIM;
#pragma unroll
    for (int m1 = 0; m1 < 16; m1++){
        float2 z = __half22float2(v[SLOT(m1)]);
        const int w_ = 16 * m1 + t;
        o0[w_]        = z.x * (1.f / 256.f) + bias0[w_];
        o0[WDIM + w_] = z.y * (1.f / 256.f) + bias0[WDIM + w_];
    }
}

extern "C" void kernel_launch(void* const* d_in, const int* in_sizes, int n_in,
                              void* d_out, int out_size) {
    const float* x  = (const float*)d_in[0];
    const float* w1 = (const float*)d_in[1];
    const float* b1 = (const float*)d_in[2];
    const float* w2 = (const float*)d_in[3];
    const float* b2 = (const float*)d_in[4];
    float* out = (float*)d_out;

    const int SMEM_ROW = 19456;
    const int SMEM_COL = 25856;

    cudaFuncSetAttribute(k_rowfft,     cudaFuncAttributeMaxDynamicSharedMemorySize, SMEM_ROW);
    cudaFuncSetAttribute(k_colfft_mlp, cudaFuncAttributeMaxDynamicSharedMemorySize, SMEM_COL);
    cudaFuncSetAttribute(k_rowifft,    cudaFuncAttributeMaxDynamicSharedMemorySize, SMEM_ROW);

    k_rowfft<<<BSZ * CSZ * (HDIM / 32), 256, SMEM_ROW>>>(x);
    k_colfft_mlp<<<BSZ * NBLK * WF, 256, SMEM_COL>>>(w1, b1, w2, b2);
    k_rowifft<<<BSZ * CSZ * (HDIM / 32), 256, SMEM_ROW>>>(x, out);
}

// round 9
// speedup vs baseline: 2.0290x; 1.2830x over previous
#include <cuda_runtime.h>
#include <cuda_fp16.h>
#include <math.h>

#define HDIM 256
#define WDIM 256
#define WF   129
#define BSZ  4
#define CSZ  128
#define NBLK 8

// scratch spectrum buffer, layout [b, c, wf, h] as half2 (~67 MB)
__device__ __half2 g_buf[(size_t)BSZ * CSZ * WF * HDIM];

// ---------------- packed half2 complex helpers ----------------
__device__ __forceinline__ __half2 hswap(__half2 a){ return __lowhigh2highlow(a); }

template<bool INV>
__device__ __forceinline__ __half2 mul_i_h(__half2 a){
    const __half2 sp = __floats2half2_rn(INV ? -1.f : 1.f, INV ? 1.f : -1.f);
    return __hmul2(hswap(a), sp);
}

template<bool INV>
__device__ __forceinline__ void bf4h(__half2& x0, __half2& x1, __half2& x2, __half2& x3){
    __half2 t0 = __hadd2(x0, x2), t1 = __hsub2(x0, x2);
    __half2 t2 = __hadd2(x1, x3), t3 = __hsub2(x1, x3);
    __half2 s3 = hswap(t3);
    const __half2 sp = __floats2half2_rn(INV ? -1.f : 1.f, INV ? 1.f : -1.f);
    const __half2 sn = __floats2half2_rn(INV ? 1.f : -1.f, INV ? -1.f : 1.f);
    x0 = __hadd2(t0, t2);
    x2 = __hsub2(t0, t2);
    x1 = __hfma2(s3, sp, t1);
    x3 = __hfma2(s3, sn, t1);
}

__device__ __forceinline__ __half2 cmulh_c(__half2 v, float wr, float wi_s){
    __half2 wrr = __floats2half2_rn(wr, wr);
    __half2 wni = __floats2half2_rn(-wi_s, wi_s);
    return __hfma2(hswap(v), wni, __hmul2(v, wrr));
}

__device__ __forceinline__ __half2 cmulh_t(__half2 v, uint2 u){
    return __hfma2(hswap(v), *(__half2*)&u.y, __hmul2(v, *(__half2*)&u.x));
}

template<bool INV>
__device__ __forceinline__ void dft16h(__half2 v[16]){
    const float S = INV ? 1.f : -1.f;
    bf4h<INV>(v[0], v[4], v[8],  v[12]);
    bf4h<INV>(v[1], v[5], v[9],  v[13]);
    bf4h<INV>(v[2], v[6], v[10], v[14]);
    bf4h<INV>(v[3], v[7], v[11], v[15]);
    v[5]  = cmulh_c(v[5],   0.92387953f, S*0.38268343f);
    v[9]  = cmulh_c(v[9],   0.70710678f, S*0.70710678f);
    v[13] = cmulh_c(v[13],  0.38268343f, S*0.92387953f);
    v[6]  = cmulh_c(v[6],   0.70710678f, S*0.70710678f);
    v[10] = mul_i_h<INV>(v[10]);
    v[14] = cmulh_c(v[14], -0.70710678f, S*0.70710678f);
    v[7]  = cmulh_c(v[7],   0.38268343f, S*0.92387953f);
    v[11] = cmulh_c(v[11], -0.70710678f, S*0.70710678f);
    v[15] = cmulh_c(v[15], -0.92387953f, -S*0.38268343f);
    bf4h<INV>(v[0],  v[1],  v[2],  v[3]);
    bf4h<INV>(v[4],  v[5],  v[6],  v[7]);
    bf4h<INV>(v[8],  v[9],  v[10], v[11]);
    bf4h<INV>(v[12], v[13], v[14], v[15]);
}

#define SLOT(k) ((((k) & 3) << 2) | ((k) >> 2))

__device__ __forceinline__ void build_twh(uint2* twf, uint2* twi, int tid){
    float s, c;
    sincosf((float)tid * (-6.283185307179586f / 256.f), &s, &c);
    __half2 cc = __floats2half2_rn(c, c);
    __half2 nf = __floats2half2_rn(-s, s);
    __half2 ni = __floats2half2_rn(s, -s);
    uint2 u;
    u.x = *(unsigned int*)&cc;
    if (twf){ u.y = *(unsigned int*)&nf; twf[tid] = u; }
    if (twi){ u.y = *(unsigned int*)&ni; twi[tid] = u; }
}

// ---------------- MMA helpers ----------------
__device__ __forceinline__ unsigned s2u(const void* p){
    return (unsigned)__cvta_generic_to_shared(p);
}
__device__ __forceinline__ void ldmx4(unsigned* r, unsigned a){
    asm volatile("ldmatrix.sync.aligned.m8n8.x4.shared.b16 {%0,%1,%2,%3}, [%4];"
        : "=r"(r[0]), "=r"(r[1]), "=r"(r[2]), "=r"(r[3]) : "r"(a));
}
__device__ __forceinline__ void ldmx2t(unsigned& b0, unsigned& b1, unsigned a){
    asm volatile("ldmatrix.sync.aligned.m8n8.x2.trans.shared.b16 {%0,%1}, [%2];"
        : "=r"(b0), "=r"(b1) : "r"(a));
}
__device__ __forceinline__ void stmx2(unsigned a, unsigned r0, unsigned r1){
    asm volatile("stmatrix.sync.aligned.m8n8.x2.shared.b16 [%0], {%1,%2};"
        :: "r"(a), "r"(r0), "r"(r1) : "memory");
}
__device__ __forceinline__ void mma16816(float* c, const unsigned* a,
                                         unsigned b0, unsigned b1){
    asm volatile(
        "mma.sync.aligned.m16n8k16.row.col.f32.f16.f16.f32 "
        "{%0,%1,%2,%3}, {%4,%5,%6,%7}, {%8,%9}, {%0,%1,%2,%3};"
        : "+f"(c[0]), "+f"(c[1]), "+f"(c[2]), "+f"(c[3])
        : "r"(a[0]), "r"(a[1]), "r"(a[2]), "r"(a[3]), "r"(b0), "r"(b1));
}
__device__ __forceinline__ unsigned packh2(float a, float b){
    __half2 h = __floats2half2_rn(a, b);
    return *(unsigned*)&h;
}

// ---------------------------------------------------------------------------
// K1: row rfft, fp16 FFT. CTA = 32 rows, 2 real rows packed per complex FFT.
// ---------------------------------------------------------------------------
__global__ void __launch_bounds__(256) k_rowfft(const float* __restrict__ x){
    extern __shared__ char smraw[];
    __half2* bufh = (__half2*)smraw;               // 4352 h2  [0, 17408)
    uint2*   twf  = (uint2*)(smraw + 17408);       // 256 u2

    const int tid = threadIdx.x;
    const int f = tid >> 4, t = tid & 15;
    const int bc = blockIdx.x >> 3;
    const int h0 = (blockIdx.x & 7) << 5;

    build_twh(twf, nullptr, tid);

    const float* r0 = x + ((size_t)bc * HDIM + h0 + 2 * f) * WDIM;
    __half2 v[16];
#pragma unroll
    for (int n1 = 0; n1 < 16; n1++)
        v[n1] = __floats2half2_rn(r0[16 * n1 + t], r0[WDIM + 16 * n1 + t]);
    dft16h<false>(v);
    __syncthreads();

#pragma unroll
    for (int k1 = 0; k1 < 16; k1++){
        __half2 bv = v[SLOT(k1)];
        if (k1) bv = cmulh_t(bv, twf[t * k1]);
        bufh[f * 272 + k1 * 17 + t] = bv;
    }
    __syncthreads();
#pragma unroll
    for (int n2 = 0; n2 < 16; n2++)
        v[n2] = bufh[f * 272 + t * 17 + n2];
    __syncthreads();
    dft16h<false>(v);
#pragma unroll
    for (int k2 = 0; k2 < 16; k2++)
        bufh[f * 257 + t + 16 * k2] = v[SLOT(k2)];
    __syncthreads();

    __half2* dst = g_buf + (size_t)bc * WF * HDIM;
    for (int e = tid; e < WF * 32; e += 256){
        const int wf = e >> 5, r = e & 31, fp = r >> 1;
        float2 Z1 = __half22float2(bufh[fp * 257 + wf]);
        float2 Z2 = __half22float2(bufh[fp * 257 + ((256 - wf) & 255)]);
        float2 val = (r & 1)
            ? make_float2((Z1.y + Z2.y) * 0.5f, (Z2.x - Z1.x) * 0.5f)
            : make_float2((Z1.x + Z2.x) * 0.5f, (Z1.y - Z2.y) * 0.5f);
        dst[(size_t)wf * HDIM + h0 + r] =
            __floats2half2_rn(val.x * (1.f / 256.f), val.y * (1.f / 256.f));
    }
}

// ---------------------------------------------------------------------------
// K2: packed-fp16 column FFT + HMMA block MLP + inverse FFT, in-place g_buf.
// MLP: Y[32,256] = W_stack[32,32] @ X_stack[32,256] per layer via m16n8k16.
// ---------------------------------------------------------------------------
__global__ void __launch_bounds__(256, 3) k_colfft_mlp(
        const float* __restrict__ w1g, const float* __restrict__ b1g,
        const float* __restrict__ w2g, const float* __restrict__ b2g){
    extern __shared__ char smraw[];
    __half2* bufh = (__half2*)smraw;               // T/Abuf alias [0, 17408)
    uint2*   twf  = (uint2*)(smraw + 17408);       // [17408, 19456)
    uint2*   twi  = (uint2*)(smraw + 19456);       // [19456, 21504)
    __half*  Xs   = (__half*)(smraw + 21504);      // 32 x 264    [21504, 38400)
    __half*  Hs   = (__half*)(smraw + 38400);      // 32 x 264    [38400, 55296)
    __half*  W1s  = (__half*)(smraw + 55296);      // 32 x 40     [55296, 57856)
    __half*  W2s  = (__half*)(smraw + 57856);      // 32 x 40     [57856, 60416)
    float*   b1s  = (float*)(smraw + 60416);       // 32          [60416, 60544)
    float*   b2s  = (float*)(smraw + 60544);       // 32          [60544, 60672)

    const int tid = threadIdx.x;
    const int f = tid >> 4, t = tid & 15;
    const int lane = tid & 31, wrp = tid >> 5;
    const int g = lane >> 2, tg = lane & 3;
    const int wf = blockIdx.x % WF;
    const int bk = blockIdx.x / WF;
    const int k = bk & 7, b = bk >> 3;

    build_twh(twf, twi, tid);
    {   // W_stack = [[Wr, -Wi],[Wi, Wr]]; w1/w2 are [2][8][16 in][16 out]
        const int i = tid >> 4, o = tid & 15;
        float wr = w1g[k * 256 + i * 16 + o], wi = w1g[2048 + k * 256 + i * 16 + o];
        W1s[o * 40 + i]             = __float2half(wr);
        W1s[o * 40 + 16 + i]        = __float2half(-wi);
        W1s[(16 + o) * 40 + i]      = __float2half(wi);
        W1s[(16 + o) * 40 + 16 + i] = __float2half(wr);
        wr = w2g[k * 256 + i * 16 + o]; wi = w2g[2048 + k * 256 + i * 16 + o];
        W2s[o * 40 + i]             = __float2half(wr);
        W2s[o * 40 + 16 + i]        = __float2half(-wi);
        W2s[(16 + o) * 40 + i]      = __float2half(wi);
        W2s[(16 + o) * 40 + 16 + i] = __float2half(wr);
    }
    if (tid < 16){
        b1s[tid] = b1g[k * 16 + tid];  b1s[16 + tid] = b1g[128 + k * 16 + tid];
        b2s[tid] = b2g[k * 16 + tid];  b2s[16 + tid] = b2g[128 + k * 16 + tid];
    }

    __half2* chp = g_buf + ((size_t)(b * CSZ + k * 16 + f) * WF + wf) * HDIM;

    // ---- forward column FFT ----
    __half2 v[16];
#pragma unroll
    for (int n1 = 0; n1 < 16; n1++) v[n1] = chp[16 * n1 + t];
    dft16h<false>(v);
    __syncthreads();                               // tables + weights ready
#pragma unroll
    for (int k1 = 0; k1 < 16; k1++){
        __half2 bv = v[SLOT(k1)];
        if (k1) bv = cmulh_t(bv, twf[t * k1]);
        bufh[f * 272 + k1 * 17 + t] = bv;          // T write
    }
    __syncthreads();
#pragma unroll
    for (int n2 = 0; n2 < 16; n2++) v[n2] = bufh[f * 272 + t * 17 + n2];  // T read
    dft16h<false>(v);
#pragma unroll
    for (int k2 = 0; k2 < 16; k2++){               // X_stack write (re/im rows)
        const int bin = t + (k2 << 4);
        __half2 z = v[SLOT(k2)];
        Xs[f * 264 + bin]        = __low2half(z);
        Xs[(16 + f) * 264 + bin] = __high2half(z);
    }
    __syncthreads();                               // Xs complete; T dead

    // ---- MLP via HMMA: each warp owns 32 columns ----
    {
        const unsigned rowsel = lane & 15;
        const unsigned XsB = s2u(Xs), HsB = s2u(Hs);
        float b1v0 = b1s[g], b1v1 = b1s[g + 8], b1v2 = b1s[16 + g], b1v3 = b1s[24 + g];

        unsigned A1[4][4];
#pragma unroll
        for (int m = 0; m < 2; m++)
#pragma unroll
            for (int kt = 0; kt < 2; kt++)
                ldmx4(A1[m * 2 + kt],
                      s2u(W1s) + (((m * 16 + rowsel) * 40 + kt * 16 + (lane >> 4) * 8) << 1));

#pragma unroll
        for (int nt = 0; nt < 4; nt++){
            const int n0 = wrp * 32 + nt * 8;
            unsigned bx0, bx1, by0, by1;
            ldmx2t(bx0, bx1, XsB + ((rowsel * 264 + n0) << 1));
            ldmx2t(by0, by1, XsB + (((16 + rowsel) * 264 + n0) << 1));
            float cr[4] = {0.f, 0.f, 0.f, 0.f}, ci[4] = {0.f, 0.f, 0.f, 0.f};
            mma16816(cr, A1[0], bx0, bx1);
            mma16816(cr, A1[1], by0, by1);
            mma16816(ci, A1[2], bx0, bx1);
            mma16816(ci, A1[3], by0, by1);
            unsigned hr0 = packh2(fmaxf(cr[0] + b1v0, 0.f), fmaxf(cr[1] + b1v0, 0.f));
            unsigned hr1 = packh2(fmaxf(cr[2] + b1v1, 0.f), fmaxf(cr[3] + b1v1, 0.f));
            unsigned hi0 = packh2(fmaxf(ci[0] + b1v2, 0.f), fmaxf(ci[1] + b1v2, 0.f));
            unsigned hi1 = packh2(fmaxf(ci[2] + b1v3, 0.f), fmaxf(ci[3] + b1v3, 0.f));
            stmx2(HsB + ((rowsel * 264 + n0) << 1), hr0, hr1);
            stmx2(HsB + (((16 + rowsel) * 264 + n0) << 1), hi0, hi1);
        }
        __syncwarp();

        unsigned A2[4][4];
#pragma unroll
        for (int m = 0; m < 2; m++)
#pragma unroll
            for (int kt = 0; kt < 2; kt++)
                ldmx4(A2[m * 2 + kt],
                      s2u(W2s) + (((m * 16 + rowsel) * 40 + kt * 16 + (lane >> 4) * 8) << 1));
        float b2v0 = b2s[g], b2v1 = b2s[g + 8], b2v2 = b2s[16 + g], b2v3 = b2s[24 + g];

#pragma unroll
        for (int nt = 0; nt < 4; nt++){
            const int n0 = wrp * 32 + nt * 8;
            unsigned bx0, bx1, by0, by1;
            ldmx2t(bx0, bx1, HsB + ((rowsel * 264 + n0) << 1));
            ldmx2t(by0, by1, HsB + (((16 + rowsel) * 264 + n0) << 1));
            float cr[4] = {0.f, 0.f, 0.f, 0.f}, ci[4] = {0.f, 0.f, 0.f, 0.f};
            mma16816(cr, A2[0], bx0, bx1);
            mma16816(cr, A2[1], by0, by1);
            mma16816(ci, A2[2], bx0, bx1);
            mma16816(ci, A2[3], by0, by1);
#pragma unroll
            for (int j = 0; j < 4; j++){
                const int o = g + ((j >> 1) << 3);
                const int bin = n0 + 2 * tg + (j & 1);
                const float yr = cr[j] + ((j >> 1) ? b2v1 : b2v0);
                const float yi = ci[j] + ((j >> 1) ? b2v3 : b2v2);
                const float sr = copysignf(fmaxf(fabsf(yr) - 0.01f, 0.f), yr);
                const float si = copysignf(fmaxf(fabsf(yi) - 0.01f, 0.f), yi);
                const float xr = __half2float(Xs[o * 264 + bin]);
                const float xi = __half2float(Xs[(o + 16) * 264 + bin]);
                bufh[o * 257 + bin] = __floats2half2_rn(sr * xr - si * xi,
                                                        sr * xi + si * xr);
            }
        }
    }
    __syncthreads();                               // Abuf complete

    // ---- inverse column FFT ----
#pragma unroll
    for (int k2 = 0; k2 < 16; k2++) v[k2] = bufh[f * 257 + t + 16 * k2];  // A read
    __syncthreads();                               // A dead -> T
    dft16h<true>(v);
#pragma unroll
    for (int m2 = 0; m2 < 16; m2++){
        __half2 q = v[SLOT(m2)];
        if (m2) q = cmulh_t(q, twi[m2 * t]);
        bufh[f * 272 + m2 * 17 + t] = q;           // T write
    }
    __syncthreads();
#pragma unroll
    for (int n = 0; n < 16; n++) v[n] = bufh[f * 272 + t * 17 + n];       // T read
    dft16h<true>(v);
#pragma unroll
    for (int m1 = 0; m1 < 16; m1++)
        chp[16 * m1 + t] = v[SLOT(m1)];
}

// ---------------------------------------------------------------------------
// K3: row irfft, fp16 FFT. Hermitian extension + edge-bin imag zeroing ==
// irfft semantics. Scale 1/256 + residual in fp32.
// ---------------------------------------------------------------------------
__global__ void __launch_bounds__(256) k_rowifft(const float* __restrict__ x,
                                                 float* __restrict__ out){
    extern __shared__ char smraw[];
    __half2* bufh = (__half2*)smraw;               // 4352 h2
    uint2*   twi  = (uint2*)(smraw + 17408);       // 256 u2

    const int tid = threadIdx.x;
    const int f = tid >> 4, t = tid & 15;
    const int bc = blockIdx.x >> 3;
    const int h0 = (blockIdx.x & 7) << 5;

    build_twh(nullptr, twi, tid);

    const __half2* gsrc = g_buf + (size_t)bc * WF * HDIM;
    for (int e = tid; e < WF * 16; e += 256){
        const int wf = e >> 4, fp = e & 15;
        uint2 u = *(const uint2*)(gsrc + (size_t)wf * HDIM + h0 + 2 * fp);
        float2 a  = __half22float2(*(__half2*)&u.x);
        float2 bq = __half22float2(*(__half2*)&u.y);
        float ay = a.y, by = bq.y;
        if (wf == 0 || wf == 128){ ay = 0.f; by = 0.f; }
        bufh[fp * 257 + wf] = __floats2half2_rn(a.x - by, ay + bq.x);
        if (wf >= 1 && wf <= 127)
            bufh[fp * 257 + 256 - wf] = __floats2half2_rn(a.x + by, bq.x - ay);
    }
    __syncthreads();

    __half2 v[16];
#pragma unroll
    for (int k2 = 0; k2 < 16; k2++) v[k2] = bufh[f * 257 + t + 16 * k2];
    __syncthreads();
    dft16h<true>(v);
#pragma unroll
    for (int m2 = 0; m2 < 16; m2++){
        __half2 q = v[SLOT(m2)];
        if (m2) q = cmulh_t(q, twi[m2 * t]);
        bufh[f * 272 + m2 * 17 + t] = q;
    }
    __syncthreads();
#pragma unroll
    for (int n = 0; n < 16; n++) v[n] = bufh[f * 272 + t * 17 + n];
    dft16h<true>(v);

    const float* bias0 = x   + ((size_t)bc * HDIM + h0 + 2 * f) * WDIM;
    float*       o0    = out + ((size_t)bc * HDIM + h0 + 2 * f) * WDIM;
#pragma unroll
    for (int m1 = 0; m1 < 16; m1++){
        float2 z = __half22float2(v[SLOT(m1)]);
        const int w_ = 16 * m1 + t;
        o0[w_]        = z.x * (1.f / 256.f) + bias0[w_];
        o0[WDIM + w_] = z.y * (1.f / 256.f) + bias0[WDIM + w_];
    }
}

extern "C" void kernel_launch(void* const* d_in, const int* in_sizes, int n_in,
                              void* d_out, int out_size) {
    const float* x  = (const float*)d_in[0];
    const float* w1 = (const float*)d_in[1];
    const float* b1 = (const float*)d_in[2];
    const float* w2 = (const float*)d_in[3];
    const float* b2 = (const float*)d_in[4];
    float* out = (float*)d_out;

    const int SMEM_ROW = 19456;
    const int SMEM_COL = 60672;

    cudaFuncSetAttribute(k_rowfft,     cudaFuncAttributeMaxDynamicSharedMemorySize, SMEM_ROW);
    cudaFuncSetAttribute(k_colfft_mlp, cudaFuncAttributeMaxDynamicSharedMemorySize, SMEM_COL);
    cudaFuncSetAttribute(k_rowifft,    cudaFuncAttributeMaxDynamicSharedMemorySize, SMEM_ROW);

    k_rowfft<<<BSZ * CSZ * (HDIM / 32), 256, SMEM_ROW>>>(x);
    k_colfft_mlp<<<BSZ * NBLK * WF, 256, SMEM_COL>>>(w1, b1, w2, b2);
    k_rowifft<<<BSZ * CSZ * (HDIM / 32), 256, SMEM_ROW>>>(x, out);
}